// round 3
// baseline (speedup 1.0000x reference)
#include <cuda_runtime.h>
#include <math.h>

#define BB 8192
#define DD 1024
#define KK 2048
#define EE 512
#define BETA 0.001f

// ---- scratch (device globals: allocation-free rule) ----
__device__ float g_S[(size_t)BB * KK];    // 64 MB: cross1 -> xp -> cross2 -> yp (reused)
__device__ float g_lat[(size_t)BB * EE];  // 16 MB
__device__ float g_b1[KK];                // mean_d pw[k,:]^2
__device__ float g_b2[KK];                // mean_e rw[:,k]^2
__device__ float g_part[8 * BB];          // per-(N-tile,row) loss partials

// ---------------- bias kernels ----------------
__global__ void k_bias1(const float* __restrict__ W) {  // W: K x D row-major
    int k = blockIdx.x;
    float s = 0.f;
    for (int d = threadIdx.x; d < DD; d += 256) {
        float v = W[(size_t)k * DD + d];
        s += v * v;
    }
    __shared__ float red[256];
    red[threadIdx.x] = s;
    __syncthreads();
    for (int o = 128; o > 0; o >>= 1) {
        if (threadIdx.x < o) red[threadIdx.x] += red[threadIdx.x + o];
        __syncthreads();
    }
    if (threadIdx.x == 0) g_b1[k] = red[0] * (1.0f / DD);
}

__global__ void k_bias2(const float* __restrict__ R) {  // R: E x K row-major
    int k = blockIdx.x * blockDim.x + threadIdx.x;
    float s = 0.f;
    for (int e = 0; e < EE; e++) {
        float v = R[(size_t)e * KK + k];
        s += v * v;
    }
    g_b2[k] = s * (1.0f / EE);
}

// ---------------- SGEMM 128x128x16, 8x8 per thread ----------------
// BT=true : C = A * B^T,  A: MxKd row-major, B: NxKd row-major (NT)
// BT=false: C = A * B,    A: MxKd row-major, B: KdxN row-major (NN)
template <bool BT>
__global__ __launch_bounds__(256) void sgemm(const float* __restrict__ A,
                                             const float* __restrict__ Bm,
                                             float* __restrict__ C,
                                             int M, int N, int Kd) {
    const int BM = 128, BN = 128, BK = 16, TM = 8, TN = 8;
    __shared__ float As[BK][BM];
    __shared__ float Bs[BK][BN];
    int tid = threadIdx.x;
    int tx = tid & 15, ty = tid >> 4;
    int brow = blockIdx.y * BM, bcol = blockIdx.x * BN;

    float acc[TM][TN] = {};
    float ar[TM], br[TN];

    for (int k0 = 0; k0 < Kd; k0 += BK) {
        // load A tile (transposed into smem)
#pragma unroll
        for (int i = 0; i < 2; i++) {
            int idx = tid + i * 256;
            int r = idx >> 2, c4 = (idx & 3) * 4;
            float4 v = *(const float4*)&A[(size_t)(brow + r) * Kd + k0 + c4];
            As[c4 + 0][r] = v.x; As[c4 + 1][r] = v.y;
            As[c4 + 2][r] = v.z; As[c4 + 3][r] = v.w;
        }
        if (BT) {
#pragma unroll
            for (int i = 0; i < 2; i++) {
                int idx = tid + i * 256;
                int r = idx >> 2, c4 = (idx & 3) * 4;
                float4 v = *(const float4*)&Bm[(size_t)(bcol + r) * Kd + k0 + c4];
                Bs[c4 + 0][r] = v.x; Bs[c4 + 1][r] = v.y;
                Bs[c4 + 2][r] = v.z; Bs[c4 + 3][r] = v.w;
            }
        } else {
#pragma unroll
            for (int i = 0; i < 2; i++) {
                int idx = tid + i * 256;
                int kk = idx >> 5, n4 = (idx & 31) * 4;
                float4 v = *(const float4*)&Bm[(size_t)(k0 + kk) * N + bcol + n4];
                *(float4*)&Bs[kk][n4] = v;
            }
        }
        __syncthreads();
#pragma unroll
        for (int kk = 0; kk < BK; kk++) {
#pragma unroll
            for (int i = 0; i < TM; i++) ar[i] = As[kk][ty * TM + i];
#pragma unroll
            for (int j = 0; j < TN; j++) br[j] = Bs[kk][tx * TN + j];
#pragma unroll
            for (int i = 0; i < TM; i++)
#pragma unroll
                for (int j = 0; j < TN; j++) acc[i][j] += ar[i] * br[j];
        }
        __syncthreads();
    }
#pragma unroll
    for (int i = 0; i < TM; i++) {
        size_t ro = (size_t)(brow + ty * TM + i) * N + bcol + tx * TN;
        *(float4*)&C[ro]     = make_float4(acc[i][0], acc[i][1], acc[i][2], acc[i][3]);
        *(float4*)&C[ro + 4] = make_float4(acc[i][4], acc[i][5], acc[i][6], acc[i][7]);
    }
}

// ---------------- last GEMM (NN) with fused loss epilogue ----------------
// recon = yp @ pw ; partial[ntile][row] = sum over this col-tile of (recon-img)^2
__global__ __launch_bounds__(256) void sgemm_loss(const float* __restrict__ A,   // yp: B x K
                                                  const float* __restrict__ Bm,  // pw: K x D
                                                  const float* __restrict__ IMG, // images: B x D
                                                  int M, int N, int Kd) {
    const int BM = 128, BN = 128, BK = 16, TM = 8, TN = 8;
    __shared__ float As[BK][BM];
    __shared__ float Bs[BK][BN];
    int tid = threadIdx.x;
    int tx = tid & 15, ty = tid >> 4;
    int brow = blockIdx.y * BM, bcol = blockIdx.x * BN;

    float acc[TM][TN] = {};
    float ar[TM], br[TN];

    for (int k0 = 0; k0 < Kd; k0 += BK) {
#pragma unroll
        for (int i = 0; i < 2; i++) {
            int idx = tid + i * 256;
            int r = idx >> 2, c4 = (idx & 3) * 4;
            float4 v = *(const float4*)&A[(size_t)(brow + r) * Kd + k0 + c4];
            As[c4 + 0][r] = v.x; As[c4 + 1][r] = v.y;
            As[c4 + 2][r] = v.z; As[c4 + 3][r] = v.w;
        }
#pragma unroll
        for (int i = 0; i < 2; i++) {
            int idx = tid + i * 256;
            int kk = idx >> 5, n4 = (idx & 31) * 4;
            float4 v = *(const float4*)&Bm[(size_t)(k0 + kk) * N + bcol + n4];
            *(float4*)&Bs[kk][n4] = v;
        }
        __syncthreads();
#pragma unroll
        for (int kk = 0; kk < BK; kk++) {
#pragma unroll
            for (int i = 0; i < TM; i++) ar[i] = As[kk][ty * TM + i];
#pragma unroll
            for (int j = 0; j < TN; j++) br[j] = Bs[kk][tx * TN + j];
#pragma unroll
            for (int i = 0; i < TM; i++)
#pragma unroll
                for (int j = 0; j < TN; j++) acc[i][j] += ar[i] * br[j];
        }
        __syncthreads();
    }
    // epilogue: per-row squared-error partials, reduced across the 16 tx lanes
    float pl[TM];
#pragma unroll
    for (int i = 0; i < TM; i++) {
        size_t ro = (size_t)(brow + ty * TM + i) * N + bcol + tx * TN;
        float s = 0.f;
#pragma unroll
        for (int j = 0; j < TN; j++) {
            float d = acc[i][j] - IMG[ro + j];
            s += d * d;
        }
        pl[i] = s;
    }
#pragma unroll
    for (int o = 1; o < 16; o <<= 1)
#pragma unroll
        for (int i = 0; i < TM; i++) pl[i] += __shfl_xor_sync(0xffffffffu, pl[i], o);
    if (tx == 0) {
#pragma unroll
        for (int i = 0; i < TM; i++)
            g_part[(size_t)blockIdx.x * BB + brow + ty * TM + i] = pl[i];
    }
}

// ---------------- row softmax over K=2048 (in place), with column bias ----------------
// p = softmax_k( BETA * (scale * cross - bias[k]) )   (per-row constants drop out)
__global__ void k_softmax(float* __restrict__ S, const float* __restrict__ bias, float scale) {
    int b = blockIdx.x;
    float* row = S + (size_t)b * KK;
    float vals[8];
    float mx = -1e30f;
#pragma unroll
    for (int i = 0; i < 8; i++) {
        int k = threadIdx.x + i * 256;
        vals[i] = BETA * (scale * row[k] - bias[k]);
        mx = fmaxf(mx, vals[i]);
    }
    __shared__ float red[256];
    red[threadIdx.x] = mx;
    __syncthreads();
    for (int o = 128; o > 0; o >>= 1) {
        if (threadIdx.x < o) red[threadIdx.x] = fmaxf(red[threadIdx.x], red[threadIdx.x + o]);
        __syncthreads();
    }
    float m = red[0];
    __syncthreads();
    float s = 0.f;
#pragma unroll
    for (int i = 0; i < 8; i++) {
        vals[i] = expf(vals[i] - m);
        s += vals[i];
    }
    red[threadIdx.x] = s;
    __syncthreads();
    for (int o = 128; o > 0; o >>= 1) {
        if (threadIdx.x < o) red[threadIdx.x] += red[threadIdx.x + o];
        __syncthreads();
    }
    float inv = 1.0f / red[0];
#pragma unroll
    for (int i = 0; i < 8; i++) {
        int k = threadIdx.x + i * 256;
        row[k] = vals[i] * inv;
    }
}

__global__ void k_final(float* __restrict__ out) {
    int b = blockIdx.x * 256 + threadIdx.x;
    float s = 0.f;
#pragma unroll
    for (int t = 0; t < 8; t++) s += g_part[(size_t)t * BB + b];
    out[b] = s * (1.0f / DD);
}

// ---------------- launch ----------------
extern "C" void kernel_launch(void* const* d_in, const int* in_sizes, int n_in,
                              void* d_out, int out_size) {
    const float* images = (const float*)d_in[0];  // (B, D)
    const float* pw     = (const float*)d_in[1];  // (K, D)
    const float* rw     = (const float*)d_in[2];  // (E, K)
    float* out = (float*)d_out;                   // (B,)

    float *S, *lat, *b1, *b2;
    cudaGetSymbolAddress((void**)&S,   g_S);
    cudaGetSymbolAddress((void**)&lat, g_lat);
    cudaGetSymbolAddress((void**)&b1,  g_b1);
    cudaGetSymbolAddress((void**)&b2,  g_b2);

    // column-norm biases
    k_bias1<<<KK, 256>>>(pw);
    k_bias2<<<KK / 256, 256>>>(rw);

    // encode: cross1 = images @ pw^T ; xp = softmax(BETA*(2/D*cross1 - b1))
    sgemm<true><<<dim3(KK / 128, BB / 128), 256>>>(images, pw, S, BB, KK, DD);
    k_softmax<<<BB, 256>>>(S, b1, 2.0f / DD);

    // lat = xp @ rw^T
    sgemm<true><<<dim3(EE / 128, BB / 128), 256>>>(S, rw, lat, BB, EE, KK);

    // decode: cross2 = lat @ rw ; yp = softmax(BETA*(2/E*cross2 - b2))
    sgemm<false><<<dim3(KK / 128, BB / 128), 256>>>(lat, rw, S, BB, KK, EE);
    k_softmax<<<BB, 256>>>(S, b2, 2.0f / EE);

    // recon = yp @ pw, fused per-row squared error
    sgemm_loss<<<dim3(DD / 128, BB / 128), 256>>>(S, pw, images, BB, DD, KK);
    k_final<<<BB / 256, 256>>>(out);
}

// round 5
// speedup vs baseline: 4.7712x; 4.7712x over previous
#include <cuda_runtime.h>
#include <cuda_bf16.h>
#include <cstdint>
#include <math.h>

#define BB 8192
#define DD 1024
#define KK 2048
#define EE 512
#define BETA 0.001f

// ---------------- scratch (device globals: allocation-free rule) ----------------
__device__ float          g_S[(size_t)BB * KK];      // 64 MB fp32 cross1/cross2
__device__ __nv_bfloat16  g_P[(size_t)BB * KK];      // 32 MB bf16 xp / yp
__device__ __nv_bfloat16  g_lat[(size_t)BB * EE];    // 8 MB bf16
__device__ __nv_bfloat16  g_imgbf[(size_t)BB * DD];  // 16 MB
__device__ __nv_bfloat16  g_pwbf[(size_t)KK * DD];   // 4 MB  (K x D)
__device__ __nv_bfloat16  g_pwT[(size_t)DD * KK];    // 4 MB  (D x K)
__device__ __nv_bfloat16  g_rwbf[(size_t)EE * KK];   // 2 MB  (E x K)
__device__ __nv_bfloat16  g_rwT[(size_t)KK * EE];    // 2 MB  (K x E)
__device__ float          g_b1[KK];
__device__ float          g_b2[KK];
__device__ float          g_part[16 * BB];

// ---------------- helpers ----------------
__device__ __forceinline__ uint32_t smem_u32(const void* p) {
    uint32_t a;
    asm("{ .reg .u64 t; cvta.to.shared.u64 t, %1; cvt.u32.u64 %0, t; }" : "=r"(a) : "l"(p));
    return a;
}
#define CP_ASYNC16(dst, src) \
    asm volatile("cp.async.cg.shared.global [%0], [%1], 16;" :: "r"(dst), "l"(src))
#define CP_COMMIT() asm volatile("cp.async.commit_group;" ::: "memory")
#define CP_WAIT(n)  asm volatile("cp.async.wait_group %0;" :: "n"(n) : "memory")

__device__ __forceinline__ void mma_bf16(float* c, const uint32_t* a, const uint32_t* b) {
    asm volatile(
        "mma.sync.aligned.m16n8k16.row.col.f32.bf16.bf16.f32 "
        "{%0,%1,%2,%3}, {%4,%5,%6,%7}, {%8,%9}, {%0,%1,%2,%3};"
        : "+f"(c[0]), "+f"(c[1]), "+f"(c[2]), "+f"(c[3])
        : "r"(a[0]), "r"(a[1]), "r"(a[2]), "r"(a[3]), "r"(b[0]), "r"(b[1]));
}

// ---------------- tensor-core NT GEMM: C[M,N] = A[M,Kd] * B[N,Kd]^T ----------------
// CTA 128x128, BK=32, 8 warps (4 x 2), warp tile 32x64.
// EPI: 0 = fp32 C, 1 = bf16 C, 2 = fused (acc - IMG)^2 row partials
#define SROW 40  // smem row stride in bf16 elems (80 B): conflict-free

__device__ __forceinline__ void cp_tile(const __nv_bfloat16* __restrict__ src, int stride,
                                        int row0, int k0, __nv_bfloat16* dst, int tid) {
#pragma unroll
    for (int t = 0; t < 2; t++) {
        int id = tid + t * 256;
        int r = id >> 2, c = id & 3;  // 4 x 16B chunks per 64B row
        uint32_t d = smem_u32(dst + r * SROW + c * 8);
        const void* s = src + (size_t)(row0 + r) * stride + k0 + c * 8;
        CP_ASYNC16(d, s);
    }
}

template <int EPI>
__global__ __launch_bounds__(256, 2) void tgemm(const __nv_bfloat16* __restrict__ A,
                                                const __nv_bfloat16* __restrict__ Bm,
                                                void* __restrict__ Cout,
                                                const float* __restrict__ IMG,
                                                int M, int N, int Kd) {
    __shared__ __align__(16) __nv_bfloat16 As[2][128 * SROW];
    __shared__ __align__(16) __nv_bfloat16 Bs[2][128 * SROW];

    int tid = threadIdx.x;
    int w = tid >> 5, lane = tid & 31;
    int g = lane >> 2, t4 = lane & 3;
    int wm = w & 3, wn = w >> 2;  // warp grid 4 (M) x 2 (N)
    int brow = blockIdx.y * 128, bcol = blockIdx.x * 128;

    float c[2][8][4] = {};  // 2 m-frags x 8 n-frags x 4 acc

    cp_tile(A, Kd, brow, 0, As[0], tid);
    cp_tile(Bm, Kd, bcol, 0, Bs[0], tid);
    CP_COMMIT();

    const int S_ = Kd / 32;
    for (int s = 0; s < S_; s++) {
        if (s + 1 < S_) {
            int nb = (s + 1) & 1;
            cp_tile(A, Kd, brow, (s + 1) * 32, As[nb], tid);
            cp_tile(Bm, Kd, bcol, (s + 1) * 32, Bs[nb], tid);
            CP_COMMIT();
            CP_WAIT(1);
        } else {
            CP_WAIT(0);
        }
        __syncthreads();

        const __nv_bfloat16* as = As[s & 1];
        const __nv_bfloat16* bs = Bs[s & 1];
#pragma unroll
        for (int kf = 0; kf < 2; kf++) {
            int kk = kf * 16;
            uint32_t a[2][4];
#pragma unroll
            for (int i = 0; i < 2; i++) {
                const __nv_bfloat16* ab = as + (wm * 32 + i * 16) * SROW + kk + 2 * t4;
                a[i][0] = *(const uint32_t*)(ab + g * SROW);
                a[i][1] = *(const uint32_t*)(ab + (g + 8) * SROW);
                a[i][2] = *(const uint32_t*)(ab + g * SROW + 8);
                a[i][3] = *(const uint32_t*)(ab + (g + 8) * SROW + 8);
            }
            uint32_t b[8][2];
#pragma unroll
            for (int j = 0; j < 8; j++) {
                const __nv_bfloat16* bb = bs + (wn * 64 + j * 8 + g) * SROW + kk + 2 * t4;
                b[j][0] = *(const uint32_t*)bb;
                b[j][1] = *(const uint32_t*)(bb + 8);
            }
#pragma unroll
            for (int i = 0; i < 2; i++)
#pragma unroll
                for (int j = 0; j < 8; j++) mma_bf16(c[i][j], a[i], b[j]);
        }
        __syncthreads();
    }

    // ---------------- epilogue ----------------
    if (EPI == 2) {
        float rs[2][2] = {};  // [mfrag][row-half]
#pragma unroll
        for (int i = 0; i < 2; i++)
#pragma unroll
            for (int h = 0; h < 2; h++) {
                int row = brow + wm * 32 + i * 16 + g + h * 8;
                float s = 0.f;
#pragma unroll
                for (int j = 0; j < 8; j++) {
                    int col = bcol + wn * 64 + j * 8 + 2 * t4;
                    float2 iv = *(const float2*)&IMG[(size_t)row * N + col];
                    float d0 = c[i][j][2 * h] - iv.x;
                    float d1 = c[i][j][2 * h + 1] - iv.y;
                    s += d0 * d0 + d1 * d1;
                }
                rs[i][h] = s;
            }
#pragma unroll
        for (int o = 1; o < 4; o <<= 1)
#pragma unroll
            for (int i = 0; i < 2; i++)
#pragma unroll
                for (int h = 0; h < 2; h++)
                    rs[i][h] += __shfl_xor_sync(0xffffffffu, rs[i][h], o);
        if (t4 == 0) {
#pragma unroll
            for (int i = 0; i < 2; i++)
#pragma unroll
                for (int h = 0; h < 2; h++) {
                    int row = brow + wm * 32 + i * 16 + g + h * 8;
                    g_part[(size_t)(blockIdx.x * 2 + wn) * BB + row] = rs[i][h];
                }
        }
    } else {
#pragma unroll
        for (int i = 0; i < 2; i++)
#pragma unroll
            for (int h = 0; h < 2; h++) {
                int row = brow + wm * 32 + i * 16 + g + h * 8;
#pragma unroll
                for (int j = 0; j < 8; j++) {
                    int col = bcol + wn * 64 + j * 8 + 2 * t4;
                    float2 v = make_float2(c[i][j][2 * h], c[i][j][2 * h + 1]);
                    if (EPI == 0) {
                        *(float2*)&((float*)Cout)[(size_t)row * N + col] = v;
                    } else {
                        *(__nv_bfloat162*)&((__nv_bfloat16*)Cout)[(size_t)row * N + col] =
                            __float22bfloat162_rn(v);
                    }
                }
            }
    }
}

// ---------------- small kernels ----------------
__global__ void k_cvt(const float* __restrict__ in, __nv_bfloat16* __restrict__ out) {
    size_t i = ((size_t)blockIdx.x * 256 + threadIdx.x) * 4;
    float4 v = *(const float4*)(in + i);
    *(__nv_bfloat162*)(out + i)     = __float22bfloat162_rn(make_float2(v.x, v.y));
    *(__nv_bfloat162*)(out + i + 2) = __float22bfloat162_rn(make_float2(v.z, v.w));
}

__global__ void k_transpose_bf(const float* __restrict__ in, __nv_bfloat16* __restrict__ out,
                               int R, int Cc) {
    __shared__ float t[32][33];
    int c0 = blockIdx.x * 32, r0 = blockIdx.y * 32;
    int x = threadIdx.x, y = threadIdx.y;  // 32 x 8
#pragma unroll
    for (int i = 0; i < 32; i += 8)
        t[y + i][x] = in[(size_t)(r0 + y + i) * Cc + c0 + x];
    __syncthreads();
#pragma unroll
    for (int i = 0; i < 32; i += 8)
        out[(size_t)(c0 + y + i) * R + r0 + x] = __float2bfloat16(t[x][y + i]);
}

__global__ void k_bias1(const float* __restrict__ W) {  // K x D
    int k = blockIdx.x;
    float s = 0.f;
    for (int d = threadIdx.x; d < DD; d += 256) {
        float v = W[(size_t)k * DD + d];
        s += v * v;
    }
    __shared__ float red[256];
    red[threadIdx.x] = s;
    __syncthreads();
    for (int o = 128; o > 0; o >>= 1) {
        if (threadIdx.x < o) red[threadIdx.x] += red[threadIdx.x + o];
        __syncthreads();
    }
    if (threadIdx.x == 0) g_b1[k] = red[0] * (1.0f / DD);
}

__global__ void k_bias2(const float* __restrict__ R) {  // E x K
    int k = blockIdx.x * blockDim.x + threadIdx.x;
    float s = 0.f;
    for (int e = 0; e < EE; e++) {
        float v = R[(size_t)e * KK + k];
        s += v * v;
    }
    g_b2[k] = s * (1.0f / EE);
}

__global__ void k_softmax(const float* __restrict__ S, __nv_bfloat16* __restrict__ P,
                          const float* __restrict__ bias, float scale) {
    int b = blockIdx.x;
    const float* row = S + (size_t)b * KK;
    __nv_bfloat16* prow = P + (size_t)b * KK;
    float vals[8];
    float mx = -1e30f;
#pragma unroll
    for (int i = 0; i < 8; i++) {
        int k = threadIdx.x + i * 256;
        vals[i] = BETA * (scale * row[k] - bias[k]);
        mx = fmaxf(mx, vals[i]);
    }
    __shared__ float red[256];
    red[threadIdx.x] = mx;
    __syncthreads();
    for (int o = 128; o > 0; o >>= 1) {
        if (threadIdx.x < o) red[threadIdx.x] = fmaxf(red[threadIdx.x], red[threadIdx.x + o]);
        __syncthreads();
    }
    float m = red[0];
    __syncthreads();
    float s = 0.f;
#pragma unroll
    for (int i = 0; i < 8; i++) {
        vals[i] = expf(vals[i] - m);
        s += vals[i];
    }
    red[threadIdx.x] = s;
    __syncthreads();
    for (int o = 128; o > 0; o >>= 1) {
        if (threadIdx.x < o) red[threadIdx.x] += red[threadIdx.x + o];
        __syncthreads();
    }
    float inv = 1.0f / red[0];
#pragma unroll
    for (int i = 0; i < 8; i++) {
        int k = threadIdx.x + i * 256;
        prow[k] = __float2bfloat16(vals[i] * inv);
    }
}

__global__ void k_final(float* __restrict__ out) {
    int b = blockIdx.x * 256 + threadIdx.x;
    float s = 0.f;
#pragma unroll
    for (int t = 0; t < 16; t++) s += g_part[(size_t)t * BB + b];
    out[b] = s * (1.0f / DD);
}

// ---------------- launch ----------------
extern "C" void kernel_launch(void* const* d_in, const int* in_sizes, int n_in,
                              void* d_out, int out_size) {
    const float* images = (const float*)d_in[0];  // (B, D)
    const float* pw     = (const float*)d_in[1];  // (K, D)
    const float* rw     = (const float*)d_in[2];  // (E, K)
    float* out = (float*)d_out;

    float* S;
    __nv_bfloat16 *P, *lat, *imgbf, *pwbf, *pwT, *rwbf, *rwT;
    float *b1, *b2;
    cudaGetSymbolAddress((void**)&S, g_S);
    cudaGetSymbolAddress((void**)&P, g_P);
    cudaGetSymbolAddress((void**)&lat, g_lat);
    cudaGetSymbolAddress((void**)&imgbf, g_imgbf);
    cudaGetSymbolAddress((void**)&pwbf, g_pwbf);
    cudaGetSymbolAddress((void**)&pwT, g_pwT);
    cudaGetSymbolAddress((void**)&rwbf, g_rwbf);
    cudaGetSymbolAddress((void**)&rwT, g_rwT);
    cudaGetSymbolAddress((void**)&b1, g_b1);
    cudaGetSymbolAddress((void**)&b2, g_b2);

    // biases + conversions + transposes
    k_bias1<<<KK, 256>>>(pw);
    k_bias2<<<KK / 256, 256>>>(rw);
    k_cvt<<<(BB * DD) / 1024, 256>>>(images, imgbf);
    k_cvt<<<(KK * DD) / 1024, 256>>>(pw, pwbf);
    k_cvt<<<(EE * KK) / 1024, 256>>>(rw, rwbf);
    k_transpose_bf<<<dim3(DD / 32, KK / 32), dim3(32, 8)>>>(pw, pwT, KK, DD);  // (D x K)
    k_transpose_bf<<<dim3(KK / 32, EE / 32), dim3(32, 8)>>>(rw, rwT, EE, KK);  // (K x E)

    // GEMM1: cross1 = imgbf @ pwbf^T  (M=B, N=K, Kd=D) -> fp32 S
    tgemm<0><<<dim3(KK / 128, BB / 128), 256>>>(imgbf, pwbf, S, nullptr, BB, KK, DD);
    k_softmax<<<BB, 256>>>(S, P, b1, 2.0f / DD);

    // GEMM2: lat = xp @ rwbf^T  (M=B, N=E, Kd=K) -> bf16 lat
    tgemm<1><<<dim3(EE / 128, BB / 128), 256>>>(P, rwbf, lat, nullptr, BB, EE, KK);

    // GEMM3: cross2 = lat @ rwT^T  (M=B, N=K, Kd=E) -> fp32 S
    tgemm<0><<<dim3(KK / 128, BB / 128), 256>>>(lat, rwT, S, nullptr, BB, KK, EE);
    k_softmax<<<BB, 256>>>(S, P, b2, 2.0f / EE);

    // GEMM4: recon = yp @ pwT^T, fused loss  (M=B, N=D, Kd=K)
    tgemm<2><<<dim3(DD / 128, BB / 128), 256>>>(P, pwT, nullptr, images, BB, DD, KK);
    k_final<<<BB / 256, 256>>>(out);
}

// round 6
// speedup vs baseline: 5.7532x; 1.2058x over previous
#include <cuda_runtime.h>
#include <cuda_bf16.h>
#include <cstdint>
#include <math.h>

#define BB 8192
#define DD 1024
#define KK 2048
#define EE 512
#define BETA 0.001f

// ---------------- scratch (device globals: allocation-free rule) ----------------
__device__ __nv_bfloat16  g_L[(size_t)BB * KK];      // 32 MB bf16 logits (reused)
__device__ __nv_bfloat16  g_P[(size_t)BB * KK];      // 32 MB bf16 xp / yp
__device__ __nv_bfloat16  g_lat[(size_t)BB * EE];    // 8 MB bf16
__device__ __nv_bfloat16  g_imgbf[(size_t)BB * DD];  // 16 MB
__device__ __nv_bfloat16  g_pwbf[(size_t)KK * DD];   // 4 MB  (K x D)
__device__ __nv_bfloat16  g_pwT[(size_t)DD * KK];    // 4 MB  (D x K)
__device__ __nv_bfloat16  g_rwbf[(size_t)EE * KK];   // 2 MB  (E x K)
__device__ __nv_bfloat16  g_rwT[(size_t)KK * EE];    // 2 MB  (K x E)
__device__ float          g_b1[KK];
__device__ float          g_b2[KK];
__device__ float          g_part[16 * BB];

// ---------------- helpers ----------------
__device__ __forceinline__ uint32_t smem_u32(const void* p) {
    uint32_t a;
    asm("{ .reg .u64 t; cvta.to.shared.u64 t, %1; cvt.u32.u64 %0, t; }" : "=r"(a) : "l"(p));
    return a;
}
#define CP_ASYNC16(dst, src) \
    asm volatile("cp.async.cg.shared.global [%0], [%1], 16;" :: "r"(dst), "l"(src))
#define CP_COMMIT() asm volatile("cp.async.commit_group;" ::: "memory")
#define CP_WAIT(n)  asm volatile("cp.async.wait_group %0;" :: "n"(n) : "memory")

#define LDMX4(r, ad)                                                                   \
    asm volatile("ldmatrix.sync.aligned.m8n8.x4.shared.b16 {%0,%1,%2,%3}, [%4];"       \
                 : "=r"((r)[0]), "=r"((r)[1]), "=r"((r)[2]), "=r"((r)[3]) : "r"(ad))

__device__ __forceinline__ void mma_bf16(float* c, const uint32_t* a, const uint32_t* b) {
    asm volatile(
        "mma.sync.aligned.m16n8k16.row.col.f32.bf16.bf16.f32 "
        "{%0,%1,%2,%3}, {%4,%5,%6,%7}, {%8,%9}, {%0,%1,%2,%3};"
        : "+f"(c[0]), "+f"(c[1]), "+f"(c[2]), "+f"(c[3])
        : "r"(a[0]), "r"(a[1]), "r"(a[2]), "r"(a[3]), "r"(b[0]), "r"(b[1]));
}

// ---------------- tensor-core NT GEMM: C[M,N] = A[M,Kd] * B[N,Kd]^T ----------------
// CTA 256x128, BK=32, 8 warps (4 M x 2 N), warp tile 64x64, 3-stage cp.async.
// EPI: 1 = bf16 C, 2 = fused (acc - IMG)^2 row partials, 3 = bf16 logits w/ bias
#define SROW 40  // smem row stride in bf16 (80 B): ldmatrix conflict-free

template <int ROWS>
__device__ __forceinline__ void cp_tile(const __nv_bfloat16* __restrict__ src, int stride,
                                        int row0, int k0, uint32_t dst_s, int tid) {
#pragma unroll
    for (int t = 0; t < ROWS / 64; t++) {
        int id = tid + t * 256;
        int r = id >> 2, c = id & 3;  // 4 x 16B chunks per 64B (32-elem) row
        uint32_t d = dst_s + (r * SROW + c * 8) * 2;
        const void* s = src + (size_t)(row0 + r) * stride + k0 + c * 8;
        CP_ASYNC16(d, s);
    }
}

template <int EPI>
__global__ __launch_bounds__(256, 1) void tgemm(const __nv_bfloat16* __restrict__ A,
                                                const __nv_bfloat16* __restrict__ Bm,
                                                void* __restrict__ Cout,
                                                const float* __restrict__ IMG,
                                                const float* __restrict__ bias,
                                                float scale, int N, int Kd) {
    extern __shared__ char smem[];
    const int ASZ = 256 * SROW * 2;  // 20480
    const int BSZ = 128 * SROW * 2;  // 10240
    const int STG = ASZ + BSZ;       // 30720

    uint32_t sb = smem_u32(smem);
    int tid = threadIdx.x;
    int w = tid >> 5, lane = tid & 31;
    int g = lane >> 2, t4 = lane & 3;
    int wm = w & 3, wn = w >> 2;  // 4 (M) x 2 (N)
    int brow = blockIdx.y * 256, bcol = blockIdx.x * 128;

    // ldmatrix per-lane row/koff
    int la = lane & 15, ka = (lane >> 4) * 8;                  // A: 16x16 frags
    int lb = (lane & 7) + ((lane >> 4) << 3), kb = ((lane >> 3) & 1) * 8;  // B

    float c[4][8][4] = {};  // 4 m-frags x 8 n-frags

    cp_tile<256>(A, Kd, brow, 0, sb, tid);
    cp_tile<128>(Bm, Kd, bcol, 0, sb + ASZ, tid);
    CP_COMMIT();
    cp_tile<256>(A, Kd, brow, 32, sb + STG, tid);
    cp_tile<128>(Bm, Kd, bcol, 32, sb + STG + ASZ, tid);
    CP_COMMIT();

    const int S_ = Kd / 32;
    for (int s = 0; s < S_; s++) {
        CP_WAIT(1);
        __syncthreads();
        uint32_t as = sb + (s % 3) * STG;
        uint32_t bs = as + ASZ;
#pragma unroll
        for (int kf = 0; kf < 2; kf++) {
            int kk = kf * 16;
            uint32_t a[4][4], b[4][4];
#pragma unroll
            for (int f = 0; f < 4; f++) {
                uint32_t ad = as + ((wm * 64 + f * 16 + la) * SROW + kk + ka) * 2;
                LDMX4(a[f], ad);
            }
#pragma unroll
            for (int jj = 0; jj < 4; jj++) {
                uint32_t bd = bs + ((wn * 64 + jj * 16 + lb) * SROW + kk + kb) * 2;
                LDMX4(b[jj], bd);
            }
#pragma unroll
            for (int i = 0; i < 4; i++)
#pragma unroll
                for (int jj = 0; jj < 4; jj++) {
                    mma_bf16(c[i][2 * jj], a[i], &b[jj][0]);
                    mma_bf16(c[i][2 * jj + 1], a[i], &b[jj][2]);
                }
        }
        if (s + 2 < S_) {
            int t = (s + 2) % 3;
            cp_tile<256>(A, Kd, brow, (s + 2) * 32, sb + t * STG, tid);
            cp_tile<128>(Bm, Kd, bcol, (s + 2) * 32, sb + t * STG + ASZ, tid);
        }
        CP_COMMIT();
    }

    // ---------------- epilogue ----------------
    int col0 = bcol + wn * 64;
    if (EPI == 2) {
#pragma unroll
        for (int i = 0; i < 4; i++)
#pragma unroll
            for (int h = 0; h < 2; h++) {
                int row = brow + wm * 64 + i * 16 + g + h * 8;
                float s = 0.f;
#pragma unroll
                for (int j = 0; j < 8; j++) {
                    int col = col0 + j * 8 + 2 * t4;
                    float2 iv = *(const float2*)&IMG[(size_t)row * N + col];
                    float d0 = c[i][j][2 * h] - iv.x;
                    float d1 = c[i][j][2 * h + 1] - iv.y;
                    s += d0 * d0 + d1 * d1;
                }
                s += __shfl_xor_sync(0xffffffffu, s, 1);
                s += __shfl_xor_sync(0xffffffffu, s, 2);
                if (t4 == 0)
                    g_part[(size_t)(blockIdx.x * 2 + wn) * BB + row] = s;
            }
    } else {
#pragma unroll
        for (int i = 0; i < 4; i++)
#pragma unroll
            for (int h = 0; h < 2; h++) {
                int row = brow + wm * 64 + i * 16 + g + h * 8;
#pragma unroll
                for (int j = 0; j < 8; j++) {
                    int col = col0 + j * 8 + 2 * t4;
                    float v0 = c[i][j][2 * h], v1 = c[i][j][2 * h + 1];
                    if (EPI == 3) {
                        float2 bv = *(const float2*)&bias[col];
                        v0 = BETA * (scale * v0 - bv.x);
                        v1 = BETA * (scale * v1 - bv.y);
                    }
                    *(__nv_bfloat162*)&((__nv_bfloat16*)Cout)[(size_t)row * N + col] =
                        __float22bfloat162_rn(make_float2(v0, v1));
                }
            }
    }
}

// ---------------- small kernels ----------------
__global__ void k_cvt(const float* __restrict__ in, __nv_bfloat16* __restrict__ out) {
    size_t i = ((size_t)blockIdx.x * 256 + threadIdx.x) * 4;
    float4 v = *(const float4*)(in + i);
    *(__nv_bfloat162*)(out + i)     = __float22bfloat162_rn(make_float2(v.x, v.y));
    *(__nv_bfloat162*)(out + i + 2) = __float22bfloat162_rn(make_float2(v.z, v.w));
}

__global__ void k_transpose_bf(const float* __restrict__ in, __nv_bfloat16* __restrict__ out,
                               int R, int Cc) {
    __shared__ float t[32][33];
    int c0 = blockIdx.x * 32, r0 = blockIdx.y * 32;
    int x = threadIdx.x, y = threadIdx.y;  // 32 x 8
#pragma unroll
    for (int i = 0; i < 32; i += 8)
        t[y + i][x] = in[(size_t)(r0 + y + i) * Cc + c0 + x];
    __syncthreads();
#pragma unroll
    for (int i = 0; i < 32; i += 8)
        out[(size_t)(c0 + y + i) * R + r0 + x] = __float2bfloat16(t[x][y + i]);
}

__global__ void k_bias1(const float* __restrict__ W) {  // K x D
    int k = blockIdx.x;
    float s = 0.f;
    for (int d = threadIdx.x; d < DD; d += 256) {
        float v = W[(size_t)k * DD + d];
        s += v * v;
    }
    __shared__ float red[256];
    red[threadIdx.x] = s;
    __syncthreads();
    for (int o = 128; o > 0; o >>= 1) {
        if (threadIdx.x < o) red[threadIdx.x] += red[threadIdx.x + o];
        __syncthreads();
    }
    if (threadIdx.x == 0) g_b1[k] = red[0] * (1.0f / DD);
}

__global__ void k_bias2(const float* __restrict__ R) {  // E x K
    int k = blockIdx.x * blockDim.x + threadIdx.x;
    float s = 0.f;
    for (int e = 0; e < EE; e++) {
        float v = R[(size_t)e * KK + k];
        s += v * v;
    }
    g_b2[k] = s * (1.0f / EE);
}

// vectorized softmax over K=2048: bf16 logits in, bf16 probs out
__global__ void k_softmax_bf(const __nv_bfloat16* __restrict__ L,
                             __nv_bfloat16* __restrict__ P) {
    int b = blockIdx.x, tid = threadIdx.x;
    int lane = tid & 31, w = tid >> 5;
    uint4 v = ((const uint4*)(L + (size_t)b * KK))[tid];
    float f[8];
    {
        __nv_bfloat162 h0 = *(__nv_bfloat162*)&v.x, h1 = *(__nv_bfloat162*)&v.y;
        __nv_bfloat162 h2 = *(__nv_bfloat162*)&v.z, h3 = *(__nv_bfloat162*)&v.w;
        float2 p0 = __bfloat1622float2(h0), p1 = __bfloat1622float2(h1);
        float2 p2 = __bfloat1622float2(h2), p3 = __bfloat1622float2(h3);
        f[0] = p0.x; f[1] = p0.y; f[2] = p1.x; f[3] = p1.y;
        f[4] = p2.x; f[5] = p2.y; f[6] = p3.x; f[7] = p3.y;
    }
    float mx = f[0];
#pragma unroll
    for (int i = 1; i < 8; i++) mx = fmaxf(mx, f[i]);
#pragma unroll
    for (int o = 16; o > 0; o >>= 1) mx = fmaxf(mx, __shfl_xor_sync(0xffffffffu, mx, o));
    __shared__ float sm[8];
    if (lane == 0) sm[w] = mx;
    __syncthreads();
    float m = sm[0];
#pragma unroll
    for (int i = 1; i < 8; i++) m = fmaxf(m, sm[i]);
    __syncthreads();
    float s = 0.f;
#pragma unroll
    for (int i = 0; i < 8; i++) {
        f[i] = __expf(f[i] - m);
        s += f[i];
    }
#pragma unroll
    for (int o = 16; o > 0; o >>= 1) s += __shfl_xor_sync(0xffffffffu, s, o);
    if (lane == 0) sm[w] = s;
    __syncthreads();
    float tot = 0.f;
#pragma unroll
    for (int i = 0; i < 8; i++) tot += sm[i];
    float inv = 1.0f / tot;
    uint4 o;
    *(__nv_bfloat162*)&o.x = __float22bfloat162_rn(make_float2(f[0] * inv, f[1] * inv));
    *(__nv_bfloat162*)&o.y = __float22bfloat162_rn(make_float2(f[2] * inv, f[3] * inv));
    *(__nv_bfloat162*)&o.z = __float22bfloat162_rn(make_float2(f[4] * inv, f[5] * inv));
    *(__nv_bfloat162*)&o.w = __float22bfloat162_rn(make_float2(f[6] * inv, f[7] * inv));
    ((uint4*)(P + (size_t)b * KK))[tid] = o;
}

__global__ void k_final(float* __restrict__ out) {
    int b = blockIdx.x * 256 + threadIdx.x;
    float s = 0.f;
#pragma unroll
    for (int t = 0; t < 16; t++) s += g_part[(size_t)t * BB + b];
    out[b] = s * (1.0f / DD);
}

// ---------------- launch ----------------
extern "C" void kernel_launch(void* const* d_in, const int* in_sizes, int n_in,
                              void* d_out, int out_size) {
    const float* images = (const float*)d_in[0];  // (B, D)
    const float* pw     = (const float*)d_in[1];  // (K, D)
    const float* rw     = (const float*)d_in[2];  // (E, K)
    float* out = (float*)d_out;

    __nv_bfloat16 *Lg, *P, *lat, *imgbf, *pwbf, *pwT, *rwbf, *rwT;
    float *b1, *b2;
    cudaGetSymbolAddress((void**)&Lg, g_L);
    cudaGetSymbolAddress((void**)&P, g_P);
    cudaGetSymbolAddress((void**)&lat, g_lat);
    cudaGetSymbolAddress((void**)&imgbf, g_imgbf);
    cudaGetSymbolAddress((void**)&pwbf, g_pwbf);
    cudaGetSymbolAddress((void**)&pwT, g_pwT);
    cudaGetSymbolAddress((void**)&rwbf, g_rwbf);
    cudaGetSymbolAddress((void**)&rwT, g_rwT);
    cudaGetSymbolAddress((void**)&b1, g_b1);
    cudaGetSymbolAddress((void**)&b2, g_b2);

    const int SMEM_SZ = 3 * (256 * SROW * 2 + 128 * SROW * 2);  // 92160
    cudaFuncSetAttribute(tgemm<1>, cudaFuncAttributeMaxDynamicSharedMemorySize, SMEM_SZ);
    cudaFuncSetAttribute(tgemm<2>, cudaFuncAttributeMaxDynamicSharedMemorySize, SMEM_SZ);
    cudaFuncSetAttribute(tgemm<3>, cudaFuncAttributeMaxDynamicSharedMemorySize, SMEM_SZ);

    // biases + conversions + transposes
    k_bias1<<<KK, 256>>>(pw);
    k_bias2<<<KK / 256, 256>>>(rw);
    k_cvt<<<(BB * DD) / 1024, 256>>>(images, imgbf);
    k_cvt<<<(KK * DD) / 1024, 256>>>(pw, pwbf);
    k_cvt<<<(EE * KK) / 1024, 256>>>(rw, rwbf);
    k_transpose_bf<<<dim3(DD / 32, KK / 32), dim3(32, 8)>>>(pw, pwT, KK, DD);  // (D x K)
    k_transpose_bf<<<dim3(KK / 32, EE / 32), dim3(32, 8)>>>(rw, rwT, EE, KK);  // (K x E)

    // GEMM1: logits1 = BETA*(2/D * imgbf@pwbf^T - b1)  (M=B, N=K, Kd=D) -> bf16 Lg
    tgemm<3><<<dim3(KK / 128, BB / 256), 256, SMEM_SZ>>>(imgbf, pwbf, Lg, nullptr, b1,
                                                         2.0f / DD, KK, DD);
    k_softmax_bf<<<BB, 256>>>(Lg, P);

    // GEMM2: lat = xp @ rwbf^T  (M=B, N=E, Kd=K) -> bf16 lat
    tgemm<1><<<dim3(EE / 128, BB / 256), 256, SMEM_SZ>>>(P, rwbf, lat, nullptr, nullptr,
                                                         0.f, EE, KK);

    // GEMM3: logits2 = BETA*(2/E * lat@rwT^T - b2)  (M=B, N=K, Kd=E) -> bf16 Lg
    tgemm<3><<<dim3(KK / 128, BB / 256), 256, SMEM_SZ>>>(lat, rwT, Lg, nullptr, b2,
                                                         2.0f / EE, KK, EE);
    k_softmax_bf<<<BB, 256>>>(Lg, P);

    // GEMM4: recon = yp @ pwT^T, fused loss  (M=B, N=D, Kd=K)
    tgemm<2><<<dim3(DD / 128, BB / 256), 256, SMEM_SZ>>>(P, pwT, nullptr, images, nullptr,
                                                         0.f, DD, KK);
    k_final<<<BB / 256, 256>>>(out);
}